// round 7
// baseline (speedup 1.0000x reference)
#include <cuda_runtime.h>

// MVKE fused kernel. Shapes fixed by the problem:
//   x[B,S,E]=[8192,100,100] f32, tag[B,T,E]=[8192,10,100], vk[V,E]=[3,100],
//   four (E,E) linear layers. Output [B,T] f32.
//
// Key identity: of1 = x@W1^T + b1 is never needed explicitly:
//   m1[b,s,v]  = x[b,s]·c1[v] + d1[v],   c1 = W1^T @ of2^T,  d1 = b1·of2
//   ws1[b,v]   = W1 @ y[b,v] + b1,       y[b,v] = sum_s sm1[s,v] x[b,s]
//   m2[b,t,v]  = tag[b,t]·c2[v] + d2[v]
//   out[b,t]   = sum_v sm2[t,v] * (ws1[b,v]·tag[b,t])

#define EE 100
#define VV 3
#define BS_ 8192
#define SS 100
#define TT 10
#define SCALE 0.1f                      // 1/sqrt(DK), DK=100
#define PADV (-4294967295.0f)
#define XPITCH 108                      // 27 float4 per row: conflict-free LDS.128 cols + scalar rows

__device__ float g_c1[VV * EE];
__device__ float g_d1[VV];
__device__ float g_c2[VV * EE];
__device__ float g_d2[VV];

__global__ void mvke_precompute(const float* __restrict__ vk,
                                const float* __restrict__ fc1_w, const float* __restrict__ fc1_b,
                                const float* __restrict__ fc2_w, const float* __restrict__ fc2_b,
                                const float* __restrict__ fc3_w, const float* __restrict__ fc3_b,
                                const float* __restrict__ fc4_w, const float* __restrict__ fc4_b) {
    __shared__ float of2s[VV * EE];
    __shared__ float of3s[VV * EE];
    int tid = threadIdx.x;
    // of2[v,e] = vk[v]·fc2_w[e] + fc2_b[e] ; of3 likewise with fc3
    for (int idx = tid; idx < VV * EE; idx += blockDim.x) {
        int v = idx / EE, e = idx % EE;
        float s2 = fc2_b[e], s3 = fc3_b[e];
        const float4* vkr = (const float4*)(vk + v * EE);
        const float4* w2r = (const float4*)(fc2_w + e * EE);
        const float4* w3r = (const float4*)(fc3_w + e * EE);
        #pragma unroll 5
        for (int j = 0; j < EE / 4; j++) {
            float4 xv = vkr[j];
            float4 a = w2r[j];
            float4 b = w3r[j];
            s2 += xv.x * a.x + xv.y * a.y + xv.z * a.z + xv.w * a.w;
            s3 += xv.x * b.x + xv.y * b.y + xv.z * b.z + xv.w * b.w;
        }
        of2s[idx] = s2;
        of3s[idx] = s3;
    }
    __syncthreads();
    // c1[v,k] = sum_e fc1_w[e,k] of2[v,e] ; c2[v,k] = sum_e fc4_w[e,k] of3[v,e]
    // Thread k owns output column k: fc1_w/fc4_w reads are coalesced across the
    // warp (consecutive k at fixed e), of2s/of3s are shared-memory broadcasts.
    if (tid < EE) {
        const int k = tid;
        float c1a[VV] = {0.f, 0.f, 0.f};
        float c2a[VV] = {0.f, 0.f, 0.f};
        #pragma unroll 4
        for (int e = 0; e < EE; e++) {
            float w1 = fc1_w[e * EE + k];
            float w4 = fc4_w[e * EE + k];
            #pragma unroll
            for (int v = 0; v < VV; v++) {
                c1a[v] += w1 * of2s[v * EE + e];
                c2a[v] += w4 * of3s[v * EE + e];
            }
        }
        #pragma unroll
        for (int v = 0; v < VV; v++) {
            g_c1[v * EE + k] = c1a[v];
            g_c2[v * EE + k] = c2a[v];
        }
    }
    if (tid < VV) {
        float d1 = 0.f, d2 = 0.f;
        for (int e = 0; e < EE; e++) {
            d1 += fc1_b[e] * of2s[tid * EE + e];
            d2 += fc4_b[e] * of3s[tid * EE + e];
        }
        g_d1[tid] = d1;
        g_d2[tid] = d2;
    }
}

// smem layout (floats)
#define OFF_XS    0
#define OFF_TAGS  (OFF_XS + SS * XPITCH)        // 10800
#define OFF_C1    (OFF_TAGS + TT * EE)          // +1000
#define OFF_C2    (OFF_C1 + VV * EE)            // +300
#define OFF_M1    (OFF_C2 + VV * EE)            // +300
#define OFF_YS    (OFF_M1 + SS * 4)             // +400
#define OFF_WS1   (OFF_YS + VV * EE)            // +300
#define OFF_M2    (OFF_WS1 + VV * EE)           // +300
#define OFF_GS    (OFF_M2 + TT * 4)             // +40
#define OFF_D12   (OFF_GS + TT * 4)             // +40
#define SMEM_FLOATS (OFF_D12 + 8)
#define SMEM_BYTES (SMEM_FLOATS * 4)

__global__ void __launch_bounds__(128, 4)
mvke_main(const float* __restrict__ x, const float* __restrict__ tag,
          const float* __restrict__ fc1_w, const float* __restrict__ fc1_b,
          float* __restrict__ out) {
    extern __shared__ float sm[];
    float* xs   = sm + OFF_XS;
    float* tags = sm + OFF_TAGS;
    float* c1s  = sm + OFF_C1;
    float* c2s  = sm + OFF_C2;
    float* m1s  = sm + OFF_M1;   // [s][4] — m1 then softmax in place
    float* ys   = sm + OFF_YS;   // [v][100]
    float* ws1s = sm + OFF_WS1;  // [v][100]
    float* m2s  = sm + OFF_M2;   // [t][4]
    float* gs   = sm + OFF_GS;   // [t][4]
    float* d12  = sm + OFF_D12;  // d1[0..2], d2 at +4

    const int tid = threadIdx.x;
    const int b = blockIdx.x;

    // ---- Phase 0: load x[b] (padded pitch), tag[b], constants ----
    {
        const float4* x4 = (const float4*)(x + (size_t)b * SS * EE);
        for (int i = tid; i < SS * EE / 4; i += blockDim.x) {
            int row = i / (EE / 4), col = i % (EE / 4);
            ((float4*)(xs + row * XPITCH))[col] = x4[i];
        }
        const float4* t4 = (const float4*)(tag + (size_t)b * TT * EE);
        for (int i = tid; i < TT * EE / 4; i += blockDim.x)
            ((float4*)tags)[i] = t4[i];
        for (int i = tid; i < VV * EE; i += blockDim.x) {
            c1s[i] = g_c1[i];
            c2s[i] = g_c2[i];
        }
        if (tid < VV) { d12[tid] = g_d1[tid]; d12[4 + tid] = g_d2[tid]; }
    }
    __syncthreads();

    // ---- Phase A: m1[s,v] = (x[s]·c1[v] + d1[v])*scale, masked if row all-zero ----
    if (tid < SS) {
        const int s = tid;
        const float b0 = d12[0], b1v = d12[1], b2v = d12[2];
        float m0 = 0.f, m1 = 0.f, m2 = 0.f, asum = 0.f;
        const float4* xr  = (const float4*)(xs + s * XPITCH);
        const float4* c0r = (const float4*)(c1s + 0 * EE);
        const float4* c1r = (const float4*)(c1s + 1 * EE);
        const float4* c2r = (const float4*)(c1s + 2 * EE);
        #pragma unroll 5
        for (int j = 0; j < EE / 4; j++) {
            float4 xv = xr[j];
            asum += fabsf(xv.x) + fabsf(xv.y) + fabsf(xv.z) + fabsf(xv.w);
            float4 a = c0r[j], bb = c1r[j], c = c2r[j];
            m0 += xv.x * a.x  + xv.y * a.y  + xv.z * a.z  + xv.w * a.w;
            m1 += xv.x * bb.x + xv.y * bb.y + xv.z * bb.z + xv.w * bb.w;
            m2 += xv.x * c.x  + xv.y * c.y  + xv.z * c.z  + xv.w * c.w;
        }
        if (asum == 0.f) {
            m1s[s * 4 + 0] = PADV; m1s[s * 4 + 1] = PADV; m1s[s * 4 + 2] = PADV;
        } else {
            m1s[s * 4 + 0] = (m0 + b0) * SCALE;
            m1s[s * 4 + 1] = (m1 + b1v) * SCALE;
            m1s[s * 4 + 2] = (m2 + b2v) * SCALE;
        }
    }
    __syncthreads();

    // ---- Phase A2: softmax over s per v (warp v handles column v), in place ----
    {
        const int w = tid >> 5, lane = tid & 31;
        if (w < VV) {
            const int v = w;
            float vals[4];
            float mx = -3.4e38f;
            #pragma unroll
            for (int i = 0; i < 4; i++) {
                int s = lane + 32 * i;
                vals[i] = (s < SS) ? m1s[s * 4 + v] : -3.4e38f;
                mx = fmaxf(mx, vals[i]);
            }
            #pragma unroll
            for (int o = 16; o; o >>= 1) mx = fmaxf(mx, __shfl_xor_sync(0xffffffffu, mx, o));
            float ex[4];
            float ssum = 0.f;
            #pragma unroll
            for (int i = 0; i < 4; i++) {
                int s = lane + 32 * i;
                ex[i] = (s < SS) ? __expf(vals[i] - mx) : 0.f;
                ssum += ex[i];
            }
            #pragma unroll
            for (int o = 16; o; o >>= 1) ssum += __shfl_xor_sync(0xffffffffu, ssum, o);
            float inv = 1.f / ssum;
            #pragma unroll
            for (int i = 0; i < 4; i++) {
                int s = lane + 32 * i;
                if (s < SS) m1s[s * 4 + v] = ex[i] * inv;
            }
        }
    }
    __syncthreads();

    // ---- Phase B: y[v,k] = sum_s sm1[s,v] * x[s,k] ----
    if (tid < EE) {
        const int k = tid;
        float a0 = 0.f, a1 = 0.f, a2 = 0.f;
        for (int s = 0; s < SS; s++) {
            float xv = xs[s * XPITCH + k];
            float4 w = ((const float4*)m1s)[s];
            a0 += w.x * xv;
            a1 += w.y * xv;
            a2 += w.z * xv;
        }
        ys[0 * EE + k] = a0;
        ys[1 * EE + k] = a1;
        ys[2 * EE + k] = a2;
    }
    __syncthreads();

    // ---- Phase C: ws1[v,e] = W1[e,:]·y[v,:] + b1[e]  (W1 stays L1-resident) ----
    if (tid < EE) {
        const int e = tid;
        float bb = __ldg(&fc1_b[e]);
        float a0 = bb, a1 = bb, a2 = bb;
        const float4* wr  = (const float4*)(fc1_w + e * EE);
        const float4* y0r = (const float4*)(ys + 0 * EE);
        const float4* y1r = (const float4*)(ys + 1 * EE);
        const float4* y2r = (const float4*)(ys + 2 * EE);
        #pragma unroll 5
        for (int j = 0; j < EE / 4; j++) {
            float4 wv = __ldg(&wr[j]);
            float4 y0 = y0r[j], y1 = y1r[j], y2 = y2r[j];
            a0 += wv.x * y0.x + wv.y * y0.y + wv.z * y0.z + wv.w * y0.w;
            a1 += wv.x * y1.x + wv.y * y1.y + wv.z * y1.z + wv.w * y1.w;
            a2 += wv.x * y2.x + wv.y * y2.y + wv.z * y2.z + wv.w * y2.w;
        }
        ws1s[0 * EE + e] = a0;
        ws1s[1 * EE + e] = a1;
        ws1s[2 * EE + e] = a2;
    }
    __syncthreads();

    // ---- Phase D: m2[t,v] = (tag[t]·c2[v] + d2[v])*scale ; g[t,v] = tag[t]·ws1[v] ----
    if (tid < TT * VV) {
        const int t = tid / VV, v = tid % VV;
        const float dv = d12[4 + v];
        float ma = 0.f, ga = 0.f;
        const float4* tr  = (const float4*)(tags + t * EE);
        const float4* cr  = (const float4*)(c2s + v * EE);
        const float4* wsr = (const float4*)(ws1s + v * EE);
        #pragma unroll 5
        for (int j = 0; j < EE / 4; j++) {
            float4 tv = tr[j];
            float4 cv = cr[j];
            float4 wv = wsr[j];
            ma += tv.x * cv.x + tv.y * cv.y + tv.z * cv.z + tv.w * cv.w;
            ga += tv.x * wv.x + tv.y * wv.y + tv.z * wv.z + tv.w * wv.w;
        }
        m2s[t * 4 + v] = (ma + dv) * SCALE;
        gs[t * 4 + v] = ga;
    }
    __syncthreads();

    // ---- Phase E: softmax over t per v (in place), then output ----
    if (tid < VV) {
        const int v = tid;
        float mx = -3.4e38f;
        #pragma unroll
        for (int t = 0; t < TT; t++) mx = fmaxf(mx, m2s[t * 4 + v]);
        float ssum = 0.f;
        float ex[TT];
        #pragma unroll
        for (int t = 0; t < TT; t++) { ex[t] = __expf(m2s[t * 4 + v] - mx); ssum += ex[t]; }
        float inv = 1.f / ssum;
        #pragma unroll
        for (int t = 0; t < TT; t++) m2s[t * 4 + v] = ex[t] * inv;
    }
    __syncthreads();
    if (tid < TT) {
        const int t = tid;
        out[(size_t)b * TT + t] = m2s[t * 4 + 0] * gs[t * 4 + 0]
                                + m2s[t * 4 + 1] * gs[t * 4 + 1]
                                + m2s[t * 4 + 2] * gs[t * 4 + 2];
    }
}

extern "C" void kernel_launch(void* const* d_in, const int* in_sizes, int n_in,
                              void* d_out, int out_size) {
    const float* x     = (const float*)d_in[0];
    const float* tag   = (const float*)d_in[1];
    const float* vk    = (const float*)d_in[2];
    const float* fc1_w = (const float*)d_in[3];
    const float* fc1_b = (const float*)d_in[4];
    const float* fc2_w = (const float*)d_in[5];
    const float* fc2_b = (const float*)d_in[6];
    const float* fc3_w = (const float*)d_in[7];
    const float* fc3_b = (const float*)d_in[8];
    const float* fc4_w = (const float*)d_in[9];
    const float* fc4_b = (const float*)d_in[10];
    float* out = (float*)d_out;

    int nb = in_sizes[0] / (SS * EE);

    cudaFuncSetAttribute(mvke_main, cudaFuncAttributeMaxDynamicSharedMemorySize, SMEM_BYTES);

    mvke_precompute<<<1, 128>>>(vk, fc1_w, fc1_b, fc2_w, fc2_b, fc3_w, fc3_b, fc4_w, fc4_b);
    mvke_main<<<nb, 128, SMEM_BYTES>>>(x, tag, fc1_w, fc1_b, out);
}